// round 15
// baseline (speedup 1.0000x reference)
#include <cuda_runtime.h>
#include <cstddef>

#define BATCH 8192
typedef unsigned long long ull;

// ---------------------------------------------------------------------------
// f32x2 packed math
// ---------------------------------------------------------------------------
__device__ __forceinline__ ull pk2(float lo, float hi) {
    ull r; asm("mov.b64 %0, {%1, %2};" : "=l"(r) : "f"(lo), "f"(hi)); return r;
}
__device__ __forceinline__ void upk2(ull v, float& lo, float& hi) {
    asm("mov.b64 {%0, %1}, %2;" : "=f"(lo), "=f"(hi) : "l"(v));
}
__device__ __forceinline__ void fma2(ull& d, ull a, ull b) {
    asm("fma.rn.f32x2 %0, %1, %2, %3;" : "=l"(d) : "l"(a), "l"(b), "l"(d));
}

// sin(v)+cos(v) = sqrt(2)*sin(v + pi/4): one MUFU instead of two
__device__ __forceinline__ float sincos1(float v) {
    return 1.41421356237f * __sinf(v + 0.78539816340f);
}

// ---------------------------------------------------------------------------
// device scratch
// ---------------------------------------------------------------------------
__device__ float g_L [4 * BATCH * 64];     // (4, B, 64) flat
__device__ float g_xc[BATCH * 256];        // (B, 64, 2, 2) flat

// conv weights: [icp(34)][jp(5)][oc(72 padded)] ulonglong2. Row = 72*16B =
// 1152B = 9 cache lines, array 128B-aligned -> warp (8 consecutive oc x 16B
// = 128B) hits exactly ONE line per LDG.
__device__ __align__(128) ulonglong2 s_c1wJ[34 * 5 * 72];
__device__ __align__(128) ulonglong2 s_c3wJ[34 * 5 * 72];
// lin weights pair-packed: [kp][o(576)] ull, lanes = ic-pair
__device__ __align__(16) ull s_l5P[850 * 576];
__device__ __align__(16) ull s_l4P[544 * 576];
__device__ __align__(16) ull s_l3P[306 * 576];
__device__ __align__(16) float s_fwT[576 * 64];   // [k][h]

// shared memory (floats): 2 batches/CTA. Activation region [0, 21216) is
// re-sliced per stage with slice size S = 272*PAD floats (PAD=(ws^2+1)&~1):
//   split stages:  b0: win=0 -> S -> 0 ; b1: win=2S -> S -> 2S
//   merged (ws3):  b0 win/out=0, scratch0=S, b1 win/out=2S, scratch1=3S
// Tile layout per slice: [corner(4)][icp(34)][PAD][lane(2)].
#define OFF_XS   21216      // 2 x 2304
#define OFF_ISP  25824      // 2 x 72
#define OFF_CELL 25968      // 4
#define SMEM_F   25972      // 103888 B -> 2 CTAs/SM

// ---------------------------------------------------------------------------
// prep: pack weights
// ---------------------------------------------------------------------------
__global__ void ow_prep(const float* __restrict__ c1w, const float* __restrict__ c3w,
                        const float* __restrict__ l5w, const float* __restrict__ l4w,
                        const float* __restrict__ l3w, const float* __restrict__ fw)
{
    const int t0 = blockIdx.x * 256 + threadIdx.x, st = gridDim.x * 256;
    for (int t = t0; t < 34 * 5 * 72; t += st) {
        const int icp = t / 360, r = t % 360, jp = r / 72, oc = r % 72;
        ulonglong2 v1 = {0ull, 0ull}, v3 = {0ull, 0ull};
        if (oc < 68) {
            const int j0 = 2 * jp, j1 = 2 * jp + 1;
            v1.x = pk2(__ldg(c1w + oc * 612 + (2 * icp) * 9 + j0),
                       __ldg(c1w + oc * 612 + (2 * icp + 1) * 9 + j0));
            v3.x = pk2(__ldg(c3w + oc * 612 + (2 * icp) * 9 + j0),
                       __ldg(c3w + oc * 612 + (2 * icp + 1) * 9 + j0));
            if (j1 < 9) {
                v1.y = pk2(__ldg(c1w + oc * 612 + (2 * icp) * 9 + j1),
                           __ldg(c1w + oc * 612 + (2 * icp + 1) * 9 + j1));
                v3.y = pk2(__ldg(c3w + oc * 612 + (2 * icp) * 9 + j1),
                           __ldg(c3w + oc * 612 + (2 * icp + 1) * 9 + j1));
            }
        }
        s_c1wJ[t] = v1;
        s_c3wJ[t] = v3;
    }
    for (int t = t0; t < 850 * 576; t += st) {
        const int kp = t / 576, o = t % 576, icp = kp / 25, pos = kp % 25;
        s_l5P[t] = pk2(__ldg(l5w + (size_t)o * 1700 + (2 * icp) * 25 + pos),
                       __ldg(l5w + (size_t)o * 1700 + (2 * icp + 1) * 25 + pos));
    }
    for (int t = t0; t < 544 * 576; t += st) {
        const int kp = t / 576, o = t % 576, icp = kp / 16, pos = kp % 16;
        s_l4P[t] = pk2(__ldg(l4w + (size_t)o * 1088 + (2 * icp) * 16 + pos),
                       __ldg(l4w + (size_t)o * 1088 + (2 * icp + 1) * 16 + pos));
    }
    for (int t = t0; t < 306 * 576; t += st) {
        const int kp = t / 576, o = t % 576, icp = kp / 9, pos = kp % 9;
        s_l3P[t] = pk2(__ldg(l3w + (size_t)o * 612 + (2 * icp) * 9 + pos),
                       __ldg(l3w + (size_t)o * 612 + (2 * icp + 1) * 9 + pos));
    }
    for (int t = t0; t < 576 * 64; t += st)
        s_fwT[t] = __ldg(fw + (size_t)(t % 64) * 576 + t / 64);
}

// ---------------------------------------------------------------------------
// one icp tile of conv taps (vectorized smem row loads, ic-pair lanes)
// ---------------------------------------------------------------------------
template <int WS>
__device__ __forceinline__ void conv_taps(ull* __restrict__ acc,
                                          const ull* __restrict__ ip,
                                          const ull* __restrict__ w2)
{
#pragma unroll
    for (int iy = 0; iy < WS; iy++) {
        const int st = iy * WS;
        ull p[WS];
        if ((st & 1) == 0) {
#pragma unroll
            for (int g = 0; g < WS / 2; g++) {
                const ulonglong2 t = *(const ulonglong2*)(ip + st + 2 * g);
                p[2 * g] = t.x; p[2 * g + 1] = t.y;
            }
            if (WS & 1) p[WS - 1] = ip[st + WS - 1];
        } else {
            p[0] = ip[st];
#pragma unroll
            for (int g = 0; g < WS / 2; g++) {
                const ulonglong2 t = *(const ulonglong2*)(ip + st + 1 + 2 * g);
                p[1 + 2 * g] = t.x; p[2 + 2 * g] = t.y;
            }
        }
#pragma unroll
        for (int ix = 0; ix < WS; ix++) {
            const ull pv = p[ix];
#pragma unroll
            for (int ky = 0; ky < 3; ky++) {
                const int oy = iy + 1 - ky;
                if (oy < 0 || oy >= WS) continue;
#pragma unroll
                for (int kx = 0; kx < 3; kx++) {
                    const int ox = ix + 1 - kx;
                    if (ox < 0 || ox >= WS) continue;
                    fma2(acc[oy * WS + ox], w2[ky * 3 + kx], pv);
                }
            }
        }
    }
}

template <int WS, bool SINCOS>
__device__ __forceinline__ void conv_store(float* __restrict__ out,
                                           const ull* __restrict__ acc,
                                           float bias, int corner, int oc)
{
    constexpr int PAD = (WS * WS + 1) & ~1;
    float* ob = out + (corner * 34 + (oc >> 1)) * (PAD * 2) + (oc & 1);
#pragma unroll
    for (int p = 0; p < WS * WS; p++) {
        float lo, hi; upk2(acc[p], lo, hi);
        float v = fmaxf(lo + hi + bias, 0.f);
        if (SINCOS) v = sincos1(v);
        ob[p * 2] = v;
    }
}

// ---------------------------------------------------------------------------
// 3x3 SAME conv, single batch. Thread map: corner = tid&3, oc = tid>>2 —
// a warp holds 8 consecutive oc x 4 corners, so each weight LDG.128 covers
// one 128B line (quad-broadcast) and input LDS are 4-address broadcasts.
// ---------------------------------------------------------------------------
template <int WS, bool SINCOS, int UNR>
__device__ __forceinline__ void conv_pair(const float* __restrict__ in,
                                          float* __restrict__ out,
                                          const ulonglong2* __restrict__ wJ,
                                          const float* __restrict__ Bv,
                                          int tid)
{
    if (tid >= 272) return;
    constexpr int PAD = (WS * WS + 1) & ~1;
    const int corner = tid & 3;
    const int oc     = tid >> 2;

    ull acc[WS * WS];
#pragma unroll
    for (int p = 0; p < WS * WS; p++) acc[p] = 0ull;
    const float bias = __ldg(Bv + oc);

    const ulonglong2* wth = wJ + oc;
    const ull* inb = (const ull*)in + corner * 34 * PAD;

#pragma unroll UNR
    for (int icp = 0; icp < 34; icp++) {
        ull w2[10];
#pragma unroll
        for (int jp = 0; jp < 5; jp++) {
            const ulonglong2 t = __ldg(wth + (icp * 5 + jp) * 72);
            w2[2 * jp] = t.x; w2[2 * jp + 1] = t.y;
        }
        conv_taps<WS>(acc, inb + icp * PAD, w2);
    }
    conv_store<WS, SINCOS>(out, acc, bias, corner, oc);
}

// ---------------------------------------------------------------------------
// Merged 2-batch conv (ws3 only: register-safe)
// ---------------------------------------------------------------------------
template <int WS, bool SINCOS>
__device__ __forceinline__ void conv_pair2(const float* __restrict__ in0,
                                           const float* __restrict__ in1,
                                           float* __restrict__ out0,
                                           float* __restrict__ out1,
                                           const ulonglong2* __restrict__ wJ,
                                           const float* __restrict__ Bv,
                                           int tid)
{
    if (tid >= 272) return;
    constexpr int PAD = (WS * WS + 1) & ~1;
    const int corner = tid & 3;
    const int oc     = tid >> 2;

    ull a0[WS * WS], a1[WS * WS];
#pragma unroll
    for (int p = 0; p < WS * WS; p++) { a0[p] = 0ull; a1[p] = 0ull; }
    const float bias = __ldg(Bv + oc);

    const ulonglong2* wth = wJ + oc;
    const ull* ib0 = (const ull*)in0 + corner * 34 * PAD;
    const ull* ib1 = (const ull*)in1 + corner * 34 * PAD;

#pragma unroll 1
    for (int icp = 0; icp < 34; icp++) {
        ull w2[10];
#pragma unroll
        for (int jp = 0; jp < 5; jp++) {
            const ulonglong2 t = __ldg(wth + (icp * 5 + jp) * 72);
            w2[2 * jp] = t.x; w2[2 * jp + 1] = t.y;
        }
        conv_taps<WS>(a0, ib0 + icp * PAD, w2);
        conv_taps<WS>(a1, ib1 + icp * PAD, w2);
    }
    conv_store<WS, SINCOS>(out0, a0, bias, corner, oc);
    conv_store<WS, SINCOS>(out1, a1, bias, corner, oc);
}

// ---------------------------------------------------------------------------
// Linear 68*WS^2 -> 576, 8 vectors (2 batches x 4 corners), k-pair vectorized.
// v0 = slice 0, v1 = slice 2S. Thread tid owns outputs (2tid, 2tid+1).
// ---------------------------------------------------------------------------
template <int WS>
__device__ __forceinline__ void lin_one(float* __restrict__ sm,
                                        const ull* __restrict__ wP,
                                        const float* __restrict__ Bv, int tid)
{
    constexpr int PP  = WS * WS;
    constexpr int PAD = (PP + 1) & ~1;
    constexpr int S   = 272 * PAD;
    constexpr int TIL = 34 * PAD;
    const ull* v0 = (const ull*)(sm);
    const ull* v1 = (const ull*)(sm + 2 * S);

    ull acc[16];   // [i(2)][vec(8)]
#pragma unroll
    for (int i = 0; i < 16; i++) acc[i] = 0ull;

#pragma unroll 1
    for (int icp = 0; icp < 34; icp++) {
        const int voff0 = icp * PAD;
        const int kp0   = icp * PP;
#pragma unroll
        for (int pp = 0; pp < PP / 2; pp++) {
            const int pos  = 2 * pp;
            const int kp   = kp0 + pos;
            const int voff = voff0 + pos;
            const ulonglong2 wa = __ldg((const ulonglong2*)(wP + (size_t)kp * 576 + 2 * tid));
            const ulonglong2 wb = __ldg((const ulonglong2*)(wP + (size_t)(kp + 1) * 576 + 2 * tid));
            {
                ulonglong2 v[4];
#pragma unroll
                for (int c = 0; c < 4; c++)
                    v[c] = *(const ulonglong2*)(v0 + c * TIL + voff);
#pragma unroll
                for (int c = 0; c < 4; c++) {
                    fma2(acc[c],     wa.x, v[c].x);
                    fma2(acc[c],     wb.x, v[c].y);
                    fma2(acc[8 + c], wa.y, v[c].x);
                    fma2(acc[8 + c], wb.y, v[c].y);
                }
            }
            {
                ulonglong2 v[4];
#pragma unroll
                for (int c = 0; c < 4; c++)
                    v[c] = *(const ulonglong2*)(v1 + c * TIL + voff);
#pragma unroll
                for (int c = 0; c < 4; c++) {
                    fma2(acc[4 + c],  wa.x, v[c].x);
                    fma2(acc[4 + c],  wb.x, v[c].y);
                    fma2(acc[12 + c], wa.y, v[c].x);
                    fma2(acc[12 + c], wb.y, v[c].y);
                }
            }
        }
        if (PP & 1) {   // tail pos = PP-1 (even index, aligned)
            const int pos  = PP - 1;
            const int kp   = kp0 + pos;
            const int voff = voff0 + pos;
            const ulonglong2 w = __ldg((const ulonglong2*)(wP + (size_t)kp * 576 + 2 * tid));
#pragma unroll
            for (int c = 0; c < 4; c++) {
                const ull a = v0[c * TIL + voff];
                const ull b = v1[c * TIL + voff];
                fma2(acc[c],      w.x, a);
                fma2(acc[8 + c],  w.y, a);
                fma2(acc[4 + c],  w.x, b);
                fma2(acc[12 + c], w.y, b);
            }
        }
    }

    __syncthreads();
#pragma unroll
    for (int i = 0; i < 2; i++) {
        const int o = 2 * tid + i;
        const float bias = __ldg(Bv + o);
        const int h = o / 9, rem = o % 9, rr = rem / 3, cc = rem % 3;
#pragma unroll
        for (int c = 0; c < 8; c++) {
            float lo, hi; upk2(acc[i * 8 + c], lo, hi);
            const float s = fmaxf(lo + hi + bias, 0.f);
            const int oy = (c & 2) ? 3 : 0, ox = (c & 1) ? 3 : 0;
            sm[OFF_XS + (c >> 2) * 2304 + h * 36 + (oy + rr) * 6 + ox + cc] = s;
        }
    }
    __syncthreads();
}

template <int WS, int UNR, bool MERGED>
__device__ __forceinline__ void stage(float* sm,
                                      const float* c1b, const float* c3b,
                                      const ull* lwP, const float* lb, int tid)
{
    constexpr int OFF = 6 - WS;
    constexpr int PAD = (WS * WS + 1) & ~1;
    constexpr int S   = 272 * PAD;
    constexpr int PER = 4 * 68 * WS * WS;

    // build fused sin+cos corner windows: b0 -> slice 0, b1 -> slice 2S
    for (int i = tid; i < 2 * PER; i += 288) {
        const int b2 = i / PER;
        const int ii = i % PER;
        const int l = ii & 1;
        int t = ii >> 1;
        const int pos = t % (WS * WS); t /= (WS * WS);
        const int icp = t % 34;
        const int corner = t / 34;
        const int ch = 2 * icp + l;
        const int gy = ((corner & 2) ? OFF : 0) + pos / WS;
        const int gx = ((corner & 1) ? OFF : 0) + pos % WS;
        float v;
        if (ch < 64)      v = sm[OFF_XS + b2 * 2304 + ch * 36 + gy * 6 + gx];
        else if (ch < 66) v = sm[OFF_CELL + b2 * 2 + ch - 64];
        else              v = sm[OFF_ISP + b2 * 72 + (ch - 66) * 36 + gy * 6 + gx];
        const int dst = b2 ? 2 * S : 0;
        sm[dst + ((corner * 34 + icp) * PAD + pos) * 2 + l] = sincos1(v);
    }
    __syncthreads();
    if (MERGED) {
        conv_pair2<WS, true >(sm, sm + 2 * S, sm + S, sm + 3 * S, s_c1wJ, c1b, tid);
        __syncthreads();
        conv_pair2<WS, false>(sm + S, sm + 3 * S, sm, sm + 2 * S, s_c3wJ, c3b, tid);
        __syncthreads();
    } else {
        conv_pair<WS, true,  UNR>(sm,         sm + S,     s_c1wJ, c1b, tid);
        __syncthreads();
        conv_pair<WS, false, UNR>(sm + S,     sm,         s_c3wJ, c3b, tid);
        __syncthreads();
        conv_pair<WS, true,  UNR>(sm + 2 * S, sm + S,     s_c1wJ, c1b, tid);
        __syncthreads();
        conv_pair<WS, false, UNR>(sm + S,     sm + 2 * S, s_c3wJ, c3b, tid);
        __syncthreads();
    }
    lin_one<WS>(sm, lwP, lb, tid);   // internal + trailing syncs
}

__global__ void __launch_bounds__(288, 2)
ow_main(const float* __restrict__ x, const float* __restrict__ cell,
        const float* __restrict__ ispg,
        const float* __restrict__ c1b, const float* __restrict__ c3b,
        const float* __restrict__ l5b, const float* __restrict__ l4b,
        const float* __restrict__ l3b, const float* __restrict__ fb)
{
    extern __shared__ float sm[];
    const int tid = threadIdx.x;
    const int bb  = blockIdx.x;           // batches 2bb, 2bb+1

    for (int i = tid; i < 2 * 2304; i += 288)
        sm[OFF_XS + i] = x[(size_t)(2 * bb) * 2304 + i];
    for (int i = tid; i < 2 * 72; i += 288)
        sm[OFF_ISP + i] = ispg[(size_t)(2 * bb) * 72 + i];
    if (tid < 4) sm[OFF_CELL + tid] = cell[2 * bb * 2 + tid];
    __syncthreads();

    stage<5, 1, false>(sm, c1b, c3b, s_l5P, l5b, tid);
    stage<4, 2, false>(sm, c1b, c3b, s_l4P, l4b, tid);
    stage<3, 2, true >(sm, c1b, c3b, s_l3P, l3b, tid);

    // final 576->64 linear per (batch, corner) + center 2x2 extraction
    for (int it = tid; it < 512; it += 288) {
        const int b2 = it >> 8, r = it & 255;
        const int corner = r >> 6, h = r & 63;
        const size_t b = 2 * (size_t)bb + b2;
        const float* xs = sm + OFF_XS + b2 * 2304;
        const int oy = (corner & 2) ? 3 : 0, ox = (corner & 1) ? 3 : 0;
        float acc = __ldg(fb + h);
        int k = 0;
        for (int ch = 0; ch < 64; ch++)
#pragma unroll
            for (int rr = 0; rr < 3; rr++)
#pragma unroll
                for (int cc = 0; cc < 3; cc++) {
                    acc = fmaf(s_fwT[k * 64 + h], xs[ch * 36 + (oy + rr) * 6 + ox + cc], acc);
                    k++;
                }
        g_L[(size_t)corner * (BATCH * 64) + b * 64 + h] = acc;

        const int h2 = r >> 2, ii = (r >> 1) & 1, jj = r & 1;
        g_xc[b * 256 + r] = xs[h2 * 36 + (2 + ii) * 6 + 2 + jj];
    }
}

// out[g] = xc_flat[g] * L_flat[g]
__global__ void ow_final(float* __restrict__ out)
{
    const int g = blockIdx.x * 256 + threadIdx.x;
    out[g] = g_xc[g] * g_L[g];
}

extern "C" void kernel_launch(void* const* d_in, const int* in_sizes, int n_in,
                              void* d_out, int out_size)
{
    const float* x    = (const float*)d_in[0];
    const float* cell = (const float*)d_in[1];
    const float* isp  = (const float*)d_in[2];
    const float* c1w  = (const float*)d_in[3];
    const float* c1b  = (const float*)d_in[4];
    const float* c3w  = (const float*)d_in[5];
    const float* c3b  = (const float*)d_in[6];
    const float* l5w  = (const float*)d_in[7];
    const float* l5b  = (const float*)d_in[8];
    const float* l4w  = (const float*)d_in[9];
    const float* l4b  = (const float*)d_in[10];
    const float* l3w  = (const float*)d_in[11];
    const float* l3b  = (const float*)d_in[12];
    const float* fw   = (const float*)d_in[13];
    const float* fb   = (const float*)d_in[14];

    const size_t smem = SMEM_F * sizeof(float);
    cudaFuncSetAttribute((const void*)ow_main,
                         cudaFuncAttributeMaxDynamicSharedMemorySize, (int)smem);

    ow_prep<<<2048, 256>>>(c1w, c3w, l5w, l4w, l3w, fw);
    ow_main<<<BATCH / 2, 288, smem>>>(x, cell, isp, c1b, c3b, l5b, l4b, l3b, fb);
    ow_final<<<(BATCH * 256) / 256, 256>>>((float*)d_out);
}

// round 16
// speedup vs baseline: 1.0630x; 1.0630x over previous
#include <cuda_runtime.h>
#include <cstddef>

#define BATCH 8192
typedef unsigned long long ull;

// ---------------------------------------------------------------------------
// f32x2 packed math
// ---------------------------------------------------------------------------
__device__ __forceinline__ ull pk2(float lo, float hi) {
    ull r; asm("mov.b64 %0, {%1, %2};" : "=l"(r) : "f"(lo), "f"(hi)); return r;
}
__device__ __forceinline__ void upk2(ull v, float& lo, float& hi) {
    asm("mov.b64 {%0, %1}, %2;" : "=f"(lo), "=f"(hi) : "l"(v));
}
__device__ __forceinline__ void fma2(ull& d, ull a, ull b) {
    asm("fma.rn.f32x2 %0, %1, %2, %3;" : "=l"(d) : "l"(a), "l"(b), "l"(d));
}

// sin(v)+cos(v) = sqrt(2)*sin(v + pi/4): one MUFU instead of two
__device__ __forceinline__ float sincos1(float v) {
    return 1.41421356237f * __sinf(v + 0.78539816340f);
}

// ---------------------------------------------------------------------------
// device scratch
// ---------------------------------------------------------------------------
__device__ float g_L [4 * BATCH * 64];     // (4, B, 64) flat
__device__ float g_xc[BATCH * 256];        // (B, 64, 2, 2) flat

// conv weights: [icp(34)][jp(5)][oc(68)] ulonglong2 (j-paired, ic-pair lanes)
__device__ __align__(16) ulonglong2 s_c1wJ[34 * 5 * 68];
__device__ __align__(16) ulonglong2 s_c3wJ[34 * 5 * 68];
// lin weights pair-packed: [kp][o(576)] ull, lanes = ic-pair
__device__ __align__(16) ull s_l5P[850 * 576];
__device__ __align__(16) ull s_l4P[544 * 576];
__device__ __align__(16) ull s_l3P[306 * 576];
__device__ __align__(16) float s_fwT[576 * 64];   // [k][h]

// shared memory (floats): 2 batches/CTA. Activation region [0, 21216) is
// re-sliced per stage with slice size S = 272*PAD floats (PAD=(ws^2+1)&~1):
//   split stages:  b0: win=0 -> S -> 0 ; b1: win=2S -> S -> 2S
//   merged (ws3):  b0 win/out=0, scratch0=S, b1 win/out=2S, scratch1=3S
// Tile layout per slice: [corner(4)][icp(34)][PAD][lane(2)].
#define OFF_XS   21216      // 2 x 2304
#define OFF_ISP  25824      // 2 x 72
#define OFF_CELL 25968      // 4
#define SMEM_F   25972      // 103888 B -> 2 CTAs/SM

// ---------------------------------------------------------------------------
// prep: pack weights
// ---------------------------------------------------------------------------
__global__ void ow_prep(const float* __restrict__ c1w, const float* __restrict__ c3w,
                        const float* __restrict__ l5w, const float* __restrict__ l4w,
                        const float* __restrict__ l3w, const float* __restrict__ fw)
{
    const int t0 = blockIdx.x * 256 + threadIdx.x, st = gridDim.x * 256;
    for (int t = t0; t < 34 * 5 * 68; t += st) {
        const int icp = t / 340, r = t % 340, jp = r / 68, oc = r % 68;
        const int j0 = 2 * jp, j1 = 2 * jp + 1;
        ulonglong2 v1, v3;
        v1.x = pk2(__ldg(c1w + oc * 612 + (2 * icp) * 9 + j0),
                   __ldg(c1w + oc * 612 + (2 * icp + 1) * 9 + j0));
        v3.x = pk2(__ldg(c3w + oc * 612 + (2 * icp) * 9 + j0),
                   __ldg(c3w + oc * 612 + (2 * icp + 1) * 9 + j0));
        if (j1 < 9) {
            v1.y = pk2(__ldg(c1w + oc * 612 + (2 * icp) * 9 + j1),
                       __ldg(c1w + oc * 612 + (2 * icp + 1) * 9 + j1));
            v3.y = pk2(__ldg(c3w + oc * 612 + (2 * icp) * 9 + j1),
                       __ldg(c3w + oc * 612 + (2 * icp + 1) * 9 + j1));
        } else { v1.y = 0ull; v3.y = 0ull; }
        s_c1wJ[t] = v1;
        s_c3wJ[t] = v3;
    }
    for (int t = t0; t < 850 * 576; t += st) {
        const int kp = t / 576, o = t % 576, icp = kp / 25, pos = kp % 25;
        s_l5P[t] = pk2(__ldg(l5w + (size_t)o * 1700 + (2 * icp) * 25 + pos),
                       __ldg(l5w + (size_t)o * 1700 + (2 * icp + 1) * 25 + pos));
    }
    for (int t = t0; t < 544 * 576; t += st) {
        const int kp = t / 576, o = t % 576, icp = kp / 16, pos = kp % 16;
        s_l4P[t] = pk2(__ldg(l4w + (size_t)o * 1088 + (2 * icp) * 16 + pos),
                       __ldg(l4w + (size_t)o * 1088 + (2 * icp + 1) * 16 + pos));
    }
    for (int t = t0; t < 306 * 576; t += st) {
        const int kp = t / 576, o = t % 576, icp = kp / 9, pos = kp % 9;
        s_l3P[t] = pk2(__ldg(l3w + (size_t)o * 612 + (2 * icp) * 9 + pos),
                       __ldg(l3w + (size_t)o * 612 + (2 * icp + 1) * 9 + pos));
    }
    for (int t = t0; t < 576 * 64; t += st)
        s_fwT[t] = __ldg(fw + (size_t)(t % 64) * 576 + t / 64);
}

// ---------------------------------------------------------------------------
// one icp tile of conv taps (vectorized smem row loads, ic-pair lanes)
// ---------------------------------------------------------------------------
template <int WS>
__device__ __forceinline__ void conv_taps(ull* __restrict__ acc,
                                          const ull* __restrict__ ip,
                                          const ull* __restrict__ w2)
{
#pragma unroll
    for (int iy = 0; iy < WS; iy++) {
        const int st = iy * WS;
        ull p[WS];
        if ((st & 1) == 0) {
#pragma unroll
            for (int g = 0; g < WS / 2; g++) {
                const ulonglong2 t = *(const ulonglong2*)(ip + st + 2 * g);
                p[2 * g] = t.x; p[2 * g + 1] = t.y;
            }
            if (WS & 1) p[WS - 1] = ip[st + WS - 1];
        } else {
            p[0] = ip[st];
#pragma unroll
            for (int g = 0; g < WS / 2; g++) {
                const ulonglong2 t = *(const ulonglong2*)(ip + st + 1 + 2 * g);
                p[1 + 2 * g] = t.x; p[2 + 2 * g] = t.y;
            }
        }
#pragma unroll
        for (int ix = 0; ix < WS; ix++) {
            const ull pv = p[ix];
#pragma unroll
            for (int ky = 0; ky < 3; ky++) {
                const int oy = iy + 1 - ky;
                if (oy < 0 || oy >= WS) continue;
#pragma unroll
                for (int kx = 0; kx < 3; kx++) {
                    const int ox = ix + 1 - kx;
                    if (ox < 0 || ox >= WS) continue;
                    fma2(acc[oy * WS + ox], w2[ky * 3 + kx], pv);
                }
            }
        }
    }
}

template <int WS, bool SINCOS>
__device__ __forceinline__ void conv_store(float* __restrict__ out,
                                           const ull* __restrict__ acc,
                                           float bias, int corner, int oc)
{
    constexpr int PAD = (WS * WS + 1) & ~1;
    float* ob = out + (corner * 34 + (oc >> 1)) * (PAD * 2) + (oc & 1);
#pragma unroll
    for (int p = 0; p < WS * WS; p++) {
        float lo, hi; upk2(acc[p], lo, hi);
        float v = fmaxf(lo + hi + bias, 0.f);
        if (SINCOS) v = sincos1(v);
        ob[p * 2] = v;
    }
}

// ---------------------------------------------------------------------------
// 3x3 SAME conv, single batch (ws5/ws4: merged accs would exceed regs)
// ---------------------------------------------------------------------------
template <int WS, bool SINCOS, int UNR>
__device__ __forceinline__ void conv_pair(const float* __restrict__ in,
                                          float* __restrict__ out,
                                          const ulonglong2* __restrict__ wJ,
                                          const float* __restrict__ Bv,
                                          int tid)
{
    if (tid >= 272) return;
    constexpr int PAD = (WS * WS + 1) & ~1;
    const int corner = tid / 68;
    const int oc     = tid % 68;

    ull acc[WS * WS];
#pragma unroll
    for (int p = 0; p < WS * WS; p++) acc[p] = 0ull;
    const float bias = __ldg(Bv + oc);

    const ulonglong2* wth = wJ + oc;
    const ull* inb = (const ull*)in + corner * 34 * PAD;

#pragma unroll UNR
    for (int icp = 0; icp < 34; icp++) {
        ull w2[10];
#pragma unroll
        for (int jp = 0; jp < 5; jp++) {
            const ulonglong2 t = __ldg(wth + (icp * 5 + jp) * 68);
            w2[2 * jp] = t.x; w2[2 * jp + 1] = t.y;
        }
        conv_taps<WS>(acc, inb + icp * PAD, w2);
    }
    conv_store<WS, SINCOS>(out, acc, bias, corner, oc);
}

// ---------------------------------------------------------------------------
// Merged 2-batch conv (ws3 only: register-safe)
// ---------------------------------------------------------------------------
template <int WS, bool SINCOS>
__device__ __forceinline__ void conv_pair2(const float* __restrict__ in0,
                                           const float* __restrict__ in1,
                                           float* __restrict__ out0,
                                           float* __restrict__ out1,
                                           const ulonglong2* __restrict__ wJ,
                                           const float* __restrict__ Bv,
                                           int tid)
{
    if (tid >= 272) return;
    constexpr int PAD = (WS * WS + 1) & ~1;
    const int corner = tid / 68;
    const int oc     = tid % 68;

    ull a0[WS * WS], a1[WS * WS];
#pragma unroll
    for (int p = 0; p < WS * WS; p++) { a0[p] = 0ull; a1[p] = 0ull; }
    const float bias = __ldg(Bv + oc);

    const ulonglong2* wth = wJ + oc;
    const ull* ib0 = (const ull*)in0 + corner * 34 * PAD;
    const ull* ib1 = (const ull*)in1 + corner * 34 * PAD;

#pragma unroll 1
    for (int icp = 0; icp < 34; icp++) {
        ull w2[10];
#pragma unroll
        for (int jp = 0; jp < 5; jp++) {
            const ulonglong2 t = __ldg(wth + (icp * 5 + jp) * 68);
            w2[2 * jp] = t.x; w2[2 * jp + 1] = t.y;
        }
        conv_taps<WS>(a0, ib0 + icp * PAD, w2);
        conv_taps<WS>(a1, ib1 + icp * PAD, w2);
    }
    conv_store<WS, SINCOS>(out0, a0, bias, corner, oc);
    conv_store<WS, SINCOS>(out1, a1, bias, corner, oc);
}

// ---------------------------------------------------------------------------
// Linear 68*WS^2 -> 576, 8 vectors (2 batches x 4 corners), k-pair vectorized.
// v0 = slice 0, v1 = slice 2S. Thread tid owns outputs (2tid, 2tid+1).
// ---------------------------------------------------------------------------
template <int WS>
__device__ __forceinline__ void lin_one(float* __restrict__ sm,
                                        const ull* __restrict__ wP,
                                        const float* __restrict__ Bv, int tid)
{
    constexpr int PP  = WS * WS;
    constexpr int PAD = (PP + 1) & ~1;
    constexpr int S   = 272 * PAD;
    constexpr int TIL = 34 * PAD;
    const ull* v0 = (const ull*)(sm);
    const ull* v1 = (const ull*)(sm + 2 * S);

    ull acc[16];   // [i(2)][vec(8)]
#pragma unroll
    for (int i = 0; i < 16; i++) acc[i] = 0ull;

#pragma unroll 1
    for (int icp = 0; icp < 34; icp++) {
        const int voff0 = icp * PAD;
        const int kp0   = icp * PP;
#pragma unroll
        for (int pp = 0; pp < PP / 2; pp++) {
            const int pos  = 2 * pp;
            const int kp   = kp0 + pos;
            const int voff = voff0 + pos;
            const ulonglong2 wa = __ldg((const ulonglong2*)(wP + (size_t)kp * 576 + 2 * tid));
            const ulonglong2 wb = __ldg((const ulonglong2*)(wP + (size_t)(kp + 1) * 576 + 2 * tid));
            {
                ulonglong2 v[4];
#pragma unroll
                for (int c = 0; c < 4; c++)
                    v[c] = *(const ulonglong2*)(v0 + c * TIL + voff);
#pragma unroll
                for (int c = 0; c < 4; c++) {
                    fma2(acc[c],     wa.x, v[c].x);
                    fma2(acc[c],     wb.x, v[c].y);
                    fma2(acc[8 + c], wa.y, v[c].x);
                    fma2(acc[8 + c], wb.y, v[c].y);
                }
            }
            {
                ulonglong2 v[4];
#pragma unroll
                for (int c = 0; c < 4; c++)
                    v[c] = *(const ulonglong2*)(v1 + c * TIL + voff);
#pragma unroll
                for (int c = 0; c < 4; c++) {
                    fma2(acc[4 + c],  wa.x, v[c].x);
                    fma2(acc[4 + c],  wb.x, v[c].y);
                    fma2(acc[12 + c], wa.y, v[c].x);
                    fma2(acc[12 + c], wb.y, v[c].y);
                }
            }
        }
        if (PP & 1) {   // tail pos = PP-1 (even index, aligned)
            const int pos  = PP - 1;
            const int kp   = kp0 + pos;
            const int voff = voff0 + pos;
            const ulonglong2 w = __ldg((const ulonglong2*)(wP + (size_t)kp * 576 + 2 * tid));
#pragma unroll
            for (int c = 0; c < 4; c++) {
                const ull a = v0[c * TIL + voff];
                const ull b = v1[c * TIL + voff];
                fma2(acc[c],      w.x, a);
                fma2(acc[8 + c],  w.y, a);
                fma2(acc[4 + c],  w.x, b);
                fma2(acc[12 + c], w.y, b);
            }
        }
    }

    __syncthreads();
#pragma unroll
    for (int i = 0; i < 2; i++) {
        const int o = 2 * tid + i;
        const float bias = __ldg(Bv + o);
        const int h = o / 9, rem = o % 9, rr = rem / 3, cc = rem % 3;
#pragma unroll
        for (int c = 0; c < 8; c++) {
            float lo, hi; upk2(acc[i * 8 + c], lo, hi);
            const float s = fmaxf(lo + hi + bias, 0.f);
            const int oy = (c & 2) ? 3 : 0, ox = (c & 1) ? 3 : 0;
            sm[OFF_XS + (c >> 2) * 2304 + h * 36 + (oy + rr) * 6 + ox + cc] = s;
        }
    }
    __syncthreads();
}

template <int WS, int UNR, bool MERGED>
__device__ __forceinline__ void stage(float* sm,
                                      const float* c1b, const float* c3b,
                                      const ull* lwP, const float* lb, int tid)
{
    constexpr int OFF = 6 - WS;
    constexpr int PAD = (WS * WS + 1) & ~1;
    constexpr int S   = 272 * PAD;

    // build fused sin+cos corner windows: b0 -> slice 0, b1 -> slice 2S.
    // One thread owns one (corner, icp, lane) triple: all indexing resolves
    // once, the pos loop is fully unrolled constant-offset LDS/MUFU/STS.
    if (tid < 272) {
        const int pr = tid >> 1;           // corner*34 + icp
        const int l  = tid & 1;
        const int corner = pr / 34;
        const int icp    = pr % 34;
        const int ch     = 2 * icp + l;
        const int oy = (corner & 2) ? OFF : 0;
        const int ox = (corner & 1) ? OFF : 0;
#pragma unroll
        for (int b2 = 0; b2 < 2; b2++) {
            float* dst = sm + (b2 ? 2 * S : 0) + pr * (PAD * 2) + l;
            if (ch < 64) {
                const float* src = sm + OFF_XS + b2 * 2304 + ch * 36 + oy * 6 + ox;
#pragma unroll
                for (int py = 0; py < WS; py++)
#pragma unroll
                    for (int px = 0; px < WS; px++)
                        dst[(py * WS + px) * 2] = sincos1(src[py * 6 + px]);
            } else if (ch < 66) {
                const float v = sincos1(sm[OFF_CELL + b2 * 2 + ch - 64]);
#pragma unroll
                for (int p = 0; p < WS * WS; p++) dst[p * 2] = v;
            } else {
                const float* src = sm + OFF_ISP + b2 * 72 + (ch - 66) * 36 + oy * 6 + ox;
#pragma unroll
                for (int py = 0; py < WS; py++)
#pragma unroll
                    for (int px = 0; px < WS; px++)
                        dst[(py * WS + px) * 2] = sincos1(src[py * 6 + px]);
            }
        }
    }
    __syncthreads();
    if (MERGED) {
        conv_pair2<WS, true >(sm, sm + 2 * S, sm + S, sm + 3 * S, s_c1wJ, c1b, tid);
        __syncthreads();
        conv_pair2<WS, false>(sm + S, sm + 3 * S, sm, sm + 2 * S, s_c3wJ, c3b, tid);
        __syncthreads();
    } else {
        conv_pair<WS, true,  UNR>(sm,         sm + S,     s_c1wJ, c1b, tid);
        __syncthreads();
        conv_pair<WS, false, UNR>(sm + S,     sm,         s_c3wJ, c3b, tid);
        __syncthreads();
        conv_pair<WS, true,  UNR>(sm + 2 * S, sm + S,     s_c1wJ, c1b, tid);
        __syncthreads();
        conv_pair<WS, false, UNR>(sm + S,     sm + 2 * S, s_c3wJ, c3b, tid);
        __syncthreads();
    }
    lin_one<WS>(sm, lwP, lb, tid);   // internal + trailing syncs
}

__global__ void __launch_bounds__(288, 2)
ow_main(const float* __restrict__ x, const float* __restrict__ cell,
        const float* __restrict__ ispg,
        const float* __restrict__ c1b, const float* __restrict__ c3b,
        const float* __restrict__ l5b, const float* __restrict__ l4b,
        const float* __restrict__ l3b, const float* __restrict__ fb)
{
    extern __shared__ float sm[];
    const int tid = threadIdx.x;
    const int bb  = blockIdx.x;           // batches 2bb, 2bb+1

    for (int i = tid; i < 2 * 2304; i += 288)
        sm[OFF_XS + i] = x[(size_t)(2 * bb) * 2304 + i];
    for (int i = tid; i < 2 * 72; i += 288)
        sm[OFF_ISP + i] = ispg[(size_t)(2 * bb) * 72 + i];
    if (tid < 4) sm[OFF_CELL + tid] = cell[2 * bb * 2 + tid];
    __syncthreads();

    stage<5, 1, false>(sm, c1b, c3b, s_l5P, l5b, tid);
    stage<4, 2, false>(sm, c1b, c3b, s_l4P, l4b, tid);
    stage<3, 2, true >(sm, c1b, c3b, s_l3P, l3b, tid);

    // final 576->64 linear per (batch, corner) + center 2x2 extraction
    for (int it = tid; it < 512; it += 288) {
        const int b2 = it >> 8, r = it & 255;
        const int corner = r >> 6, h = r & 63;
        const size_t b = 2 * (size_t)bb + b2;
        const float* xs = sm + OFF_XS + b2 * 2304;
        const int oy = (corner & 2) ? 3 : 0, ox = (corner & 1) ? 3 : 0;
        float acc = __ldg(fb + h);
        int k = 0;
        for (int ch = 0; ch < 64; ch++)
#pragma unroll
            for (int rr = 0; rr < 3; rr++)
#pragma unroll
                for (int cc = 0; cc < 3; cc++) {
                    acc = fmaf(s_fwT[k * 64 + h], xs[ch * 36 + (oy + rr) * 6 + ox + cc], acc);
                    k++;
                }
        g_L[(size_t)corner * (BATCH * 64) + b * 64 + h] = acc;

        const int h2 = r >> 2, ii = (r >> 1) & 1, jj = r & 1;
        g_xc[b * 256 + r] = xs[h2 * 36 + (2 + ii) * 6 + 2 + jj];
    }
}

// out[g] = xc_flat[g] * L_flat[g]
__global__ void ow_final(float* __restrict__ out)
{
    const int g = blockIdx.x * 256 + threadIdx.x;
    out[g] = g_xc[g] * g_L[g];
}

extern "C" void kernel_launch(void* const* d_in, const int* in_sizes, int n_in,
                              void* d_out, int out_size)
{
    const float* x    = (const float*)d_in[0];
    const float* cell = (const float*)d_in[1];
    const float* isp  = (const float*)d_in[2];
    const float* c1w  = (const float*)d_in[3];
    const float* c1b  = (const float*)d_in[4];
    const float* c3w  = (const float*)d_in[5];
    const float* c3b  = (const float*)d_in[6];
    const float* l5w  = (const float*)d_in[7];
    const float* l5b  = (const float*)d_in[8];
    const float* l4w  = (const float*)d_in[9];
    const float* l4b  = (const float*)d_in[10];
    const float* l3w  = (const float*)d_in[11];
    const float* l3b  = (const float*)d_in[12];
    const float* fw   = (const float*)d_in[13];
    const float* fb   = (const float*)d_in[14];

    const size_t smem = SMEM_F * sizeof(float);
    cudaFuncSetAttribute((const void*)ow_main,
                         cudaFuncAttributeMaxDynamicSharedMemorySize, (int)smem);

    ow_prep<<<2048, 256>>>(c1w, c3w, l5w, l4w, l3w, fw);
    ow_main<<<BATCH / 2, 288, smem>>>(x, cell, isp, c1b, c3b, l5b, l4b, l3b, fb);
    ow_final<<<(BATCH * 256) / 256, 256>>>((float*)d_out);
}